// round 17
// baseline (speedup 1.0000x reference)
#include <cuda_runtime.h>
#include <cstdint>

#define NN      100000
#define EE      1600000
#define DD      128
#define NCAT    768
#define NLAYERS 4
#define MT      782                 // ceil(NN/128)
#define MPAD    (MT * 128)          // 100096 (zero-padded tail rows)

// ---------------- scratch (static device globals) ---------------------------
__device__ float g_xhi[(size_t)MPAD * DD];
__device__ float g_xlo[(size_t)MPAD * DD];
__device__ float g_Wthi[NLAYERS * NCAT * DD];   // [l][c][k] transposed weights, tf32-hi
__device__ float g_Wtlo[NLAYERS * NCAT * DD];   // tf32-lo
__device__ float g_Y[(size_t)NN * 384];         // staging: beta_s|gamma_s|xs
__device__ float g_gamma[(size_t)NN * DD];
__device__ float g_beta[(size_t)NN * DD];
__device__ float g_h[(size_t)NN * DD];
__device__ float g_xb0[(size_t)NN * DD];
__device__ float g_xb1[(size_t)NN * DD];
__device__ int   g_counts[NN];
__device__ int   g_base[NN + 1];
__device__ int   g_cursor[NN];
__device__ int   g_srcs[EE + 8];
__device__ float g_deginv[NN];
__device__ int   g_is64;

// ---------------- helpers ----------------------------------------------------
__device__ __forceinline__ float tf32_rna(float f) {
    uint32_t u;
    asm("cvt.rna.tf32.f32 %0, %1;" : "=r"(u) : "f"(f));
    return __uint_as_float(u);
}

__global__ void detect_kernel(const void* __restrict__ eidx, int* __restrict__ is64) {
    const long long* p64 = (const long long*)eidx;
    int ok = 1;
    for (int i = 0; i < 256; i++) {
        long long v = p64[i];
        if (v < 0 || v >= NN) { ok = 0; break; }
    }
    *is64 = ok;
}

__device__ __forceinline__ int edge_at(const void* eidx, int is64, long long pos) {
    return is64 ? (int)((const long long*)eidx)[pos]
                : ((const int*)eidx)[pos];
}

// ---------------- pack weights transposed + tf32 split -----------------------
// Wt[l][c][k]; c: 0-255 W_fskip, 256-383 W_skip, 384-639 W_film, 640-767 W_lin
__global__ void pack_weights_kernel(const float* __restrict__ W_lin,
                                    const float* __restrict__ W_film,
                                    const float* __restrict__ W_skip,
                                    const float* __restrict__ W_fskip,
                                    float* __restrict__ Wthi,
                                    float* __restrict__ Wtlo) {
    int idx = blockIdx.x * blockDim.x + threadIdx.x;
    if (idx >= NLAYERS * NCAT * DD) return;
    int l = idx / (NCAT * DD);
    int rem = idx % (NCAT * DD);
    int c = rem / DD;
    int k = rem % DD;
    float v;
    if (c < 256)      v = W_fskip[(size_t)l * DD * 256 + (size_t)k * 256 + c];
    else if (c < 384) v = W_skip [(size_t)l * DD * DD  + (size_t)k * DD  + (c - 256)];
    else if (c < 640) v = W_film [(size_t)l * DD * 256 + (size_t)k * 256 + (c - 384)];
    else              v = W_lin  [(size_t)l * DD * DD  + (size_t)k * DD  + (c - 640)];
    float hi = tf32_rna(v);
    Wthi[idx] = hi;
    Wtlo[idx] = tf32_rna(v - hi);
}

// ---------------- per-layer input split --------------------------------------
__global__ void split_kernel(const float* __restrict__ xin,
                             float* __restrict__ xhi, float* __restrict__ xlo) {
    int idx = blockIdx.x * blockDim.x + threadIdx.x;
    if (idx >= NN * DD) return;
    float f = xin[idx];
    float hi = tf32_rna(f);
    xhi[idx] = hi;
    xlo[idx] = tf32_rna(f - hi);
}

// ---------------- CSR build --------------------------------------------------
__global__ void zero_int_kernel(int* __restrict__ p, int n) {
    int i = blockIdx.x * blockDim.x + threadIdx.x;
    if (i < n) p[i] = 0;
}

__global__ void count_kernel(const void* __restrict__ eidx,
                             const int* __restrict__ is64,
                             int* __restrict__ counts) {
    int e = blockIdx.x * blockDim.x + threadIdx.x;
    if (e < EE) {
        int d = edge_at(eidx, *is64, (long long)EE + e);
        atomicAdd(&counts[d], 1);
    }
}

__global__ __launch_bounds__(1024) void scan_kernel(const int* __restrict__ counts,
                                                    int* __restrict__ base,
                                                    int* __restrict__ cursor,
                                                    float* __restrict__ deginv) {
    __shared__ int warp_pref[32];
    __shared__ int chunk_tot;
    __shared__ int carry_sh;
    int tid  = threadIdx.x;
    int lane = tid & 31;
    int wid  = tid >> 5;
    if (tid == 0) carry_sh = 0;
    __syncthreads();

    for (int start = 0; start < NN; start += 1024) {
        int i = start + tid;
        int v = (i < NN) ? counts[i] : 0;

        int incl = v;
#pragma unroll
        for (int off = 1; off < 32; off <<= 1) {
            int t = __shfl_up_sync(0xffffffffu, incl, off);
            if (lane >= off) incl += t;
        }
        if (lane == 31) warp_pref[wid] = incl;
        __syncthreads();

        if (wid == 0) {
            int wv = warp_pref[lane];
            int wincl = wv;
#pragma unroll
            for (int off = 1; off < 32; off <<= 1) {
                int t = __shfl_up_sync(0xffffffffu, wincl, off);
                if (lane >= off) wincl += t;
            }
            warp_pref[lane] = wincl - wv;
            if (lane == 31) chunk_tot = wincl;
        }
        __syncthreads();

        int c = carry_sh;
        if (i < NN) {
            int excl = c + warp_pref[wid] + incl - v;
            base[i]   = excl;
            cursor[i] = excl;
            deginv[i] = 1.0f / fmaxf((float)v, 1.0f);
        }
        __syncthreads();
        if (tid == 0) carry_sh = c + chunk_tot;
        __syncthreads();
    }
    if (tid == 0) base[NN] = carry_sh;
}

__global__ void scatter_kernel(const void* __restrict__ eidx,
                               const int* __restrict__ is64,
                               int* __restrict__ cursor,
                               int* __restrict__ srcs) {
    int e = blockIdx.x * blockDim.x + threadIdx.x;
    if (e < EE) {
        int f = *is64;
        int d = edge_at(eidx, f, (long long)EE + e);
        int s = edge_at(eidx, f, (long long)e);
        int pos = atomicAdd(&cursor[d], 1);
        srcs[pos] = s;
    }
}

// ---------------- 3xTF32 tensor-core GEMM with segment-routed epilogue -------
// C[128,128] per CTA; 256 thr = 8 warps (4 M x 2 N); warp tile 32x64.
// mma.sync.m16n8k8 tf32; D += Ah*Bh + Ah*Bl + Al*Bh.
// PTX fragment layout (g = lane>>2, t = lane&3):
//   A: a0=A[g][t] a1=A[g+8][t] a2=A[g][t+4] a3=A[g+8][t+4]
//   B: b0=B[t][col g] b1=B[t+4][col g]
//   D: rows {g,g+8}, cols {2t,2t+1}
#define MMA_TF32(dd, a0, a1, a2, a3, b0, b1)                                     \
    asm volatile("mma.sync.aligned.m16n8k8.row.col.f32.tf32.tf32.f32 "           \
                 "{%0,%1,%2,%3},{%4,%5,%6,%7},{%8,%9},{%0,%1,%2,%3};"            \
                 : "+f"(dd[0]), "+f"(dd[1]), "+f"(dd[2]), "+f"(dd[3])            \
                 : "r"(a0), "r"(a1), "r"(a2), "r"(a3), "r"(b0), "r"(b1))

__global__ __launch_bounds__(256) void gemm_tf32_kernel(
    const float* __restrict__ Ah, const float* __restrict__ Al,   // [MPAD][128]
    const float* __restrict__ Bh, const float* __restrict__ Bl,   // [768][128] (layer slice)
    const float* __restrict__ bf,
    float* __restrict__ Y384, float* __restrict__ beta,
    float* __restrict__ gamma, float* __restrict__ h, int M)
{
    __shared__ float sAh[128][24], sAl[128][24], sBh[128][24], sBl[128][24]; // 48KB

    int tid = threadIdx.x;
    int bx = blockIdx.x, by = blockIdx.y;
    int lane = tid & 31, wid = tid >> 5;
    int g = lane >> 2, t = lane & 3;
    int mrow0 = (wid & 3) * 32;
    int ncol0 = (wid >> 2) * 64;

    const float* Atile_h = Ah + (size_t)by * 128 * DD;
    const float* Atile_l = Al + (size_t)by * 128 * DD;
    const float* Btile_h = Bh + (size_t)bx * 128 * DD;
    const float* Btile_l = Bl + (size_t)bx * 128 * DD;

    int lrow = tid >> 2;          // 0..63 (+64 for second half)
    int lkk  = (tid & 3) * 4;     // float4 column within 16-k chunk

    float d[2][8][4];
#pragma unroll
    for (int a = 0; a < 2; a++)
#pragma unroll
        for (int b = 0; b < 8; b++)
#pragma unroll
            for (int c = 0; c < 4; c++) d[a][b][c] = 0.0f;

    float4 pAh[2], pAl[2], pBh[2], pBl[2];

    // preload chunk 0
#pragma unroll
    for (int u = 0; u < 2; u++) {
        int row = lrow + u * 64;
        pAh[u] = *(const float4*)(Atile_h + (size_t)row * DD + lkk);
        pAl[u] = *(const float4*)(Atile_l + (size_t)row * DD + lkk);
        pBh[u] = *(const float4*)(Btile_h + (size_t)row * DD + lkk);
        pBl[u] = *(const float4*)(Btile_l + (size_t)row * DD + lkk);
    }
#pragma unroll
    for (int u = 0; u < 2; u++) {
        int row = lrow + u * 64;
        *(float4*)&sAh[row][lkk] = pAh[u];
        *(float4*)&sAl[row][lkk] = pAl[u];
        *(float4*)&sBh[row][lkk] = pBh[u];
        *(float4*)&sBl[row][lkk] = pBl[u];
    }
    __syncthreads();

    for (int ch = 0; ch < 8; ch++) {
        bool have_next = (ch + 1 < 8);
        if (have_next) {
            int kc0 = (ch + 1) * 16;
#pragma unroll
            for (int u = 0; u < 2; u++) {
                int row = lrow + u * 64;
                pAh[u] = *(const float4*)(Atile_h + (size_t)row * DD + kc0 + lkk);
                pAl[u] = *(const float4*)(Atile_l + (size_t)row * DD + kc0 + lkk);
                pBh[u] = *(const float4*)(Btile_h + (size_t)row * DD + kc0 + lkk);
                pBl[u] = *(const float4*)(Btile_l + (size_t)row * DD + kc0 + lkk);
            }
        }

#pragma unroll
        for (int ks = 0; ks < 2; ks++) {
            int k0 = ks * 8;
            uint32_t ah[2][4], al[2][4];
#pragma unroll
            for (int ma = 0; ma < 2; ma++) {
                int rb = mrow0 + ma * 16 + g;
                ah[ma][0] = __float_as_uint(sAh[rb][k0 + t]);
                ah[ma][1] = __float_as_uint(sAh[rb + 8][k0 + t]);
                ah[ma][2] = __float_as_uint(sAh[rb][k0 + t + 4]);
                ah[ma][3] = __float_as_uint(sAh[rb + 8][k0 + t + 4]);
                al[ma][0] = __float_as_uint(sAl[rb][k0 + t]);
                al[ma][1] = __float_as_uint(sAl[rb + 8][k0 + t]);
                al[ma][2] = __float_as_uint(sAl[rb][k0 + t + 4]);
                al[ma][3] = __float_as_uint(sAl[rb + 8][k0 + t + 4]);
            }
#pragma unroll
            for (int nb = 0; nb < 8; nb++) {
                int cb = ncol0 + nb * 8 + g;
                uint32_t bh0 = __float_as_uint(sBh[cb][k0 + t]);
                uint32_t bh1 = __float_as_uint(sBh[cb][k0 + t + 4]);
                uint32_t bl0 = __float_as_uint(sBl[cb][k0 + t]);
                uint32_t bl1 = __float_as_uint(sBl[cb][k0 + t + 4]);
#pragma unroll
                for (int ma = 0; ma < 2; ma++) {
                    MMA_TF32(d[ma][nb], ah[ma][0], ah[ma][1], ah[ma][2], ah[ma][3], bh0, bh1);
                    MMA_TF32(d[ma][nb], ah[ma][0], ah[ma][1], ah[ma][2], ah[ma][3], bl0, bl1);
                    MMA_TF32(d[ma][nb], al[ma][0], al[ma][1], al[ma][2], al[ma][3], bh0, bh1);
                }
            }
        }

        if (have_next) {
            __syncthreads();
#pragma unroll
            for (int u = 0; u < 2; u++) {
                int row = lrow + u * 64;
                *(float4*)&sAh[row][lkk] = pAh[u];
                *(float4*)&sAl[row][lkk] = pAl[u];
                *(float4*)&sBh[row][lkk] = pBh[u];
                *(float4*)&sBl[row][lkk] = pBl[u];
            }
            __syncthreads();
        }
    }

    // ---- segment-routed epilogue (float2 stores; cols even-aligned) ----
    int boff = (bx == 3) ? 0 : 128;
    float* dstb = (bx == 3) ? beta : gamma;
#pragma unroll
    for (int ma = 0; ma < 2; ma++) {
        int r0 = by * 128 + mrow0 + ma * 16 + g;
        int r1 = r0 + 8;
#pragma unroll
        for (int nb = 0; nb < 8; nb++) {
            int cc = ncol0 + nb * 8 + 2 * t;
            float* dp = d[ma][nb];
            if (bx < 3) {
                if (r0 < M) *(float2*)&Y384[(size_t)r0 * 384 + bx * 128 + cc] = make_float2(dp[0], dp[1]);
                if (r1 < M) *(float2*)&Y384[(size_t)r1 * 384 + bx * 128 + cc] = make_float2(dp[2], dp[3]);
            } else if (bx == 5) {
                if (r0 < M) *(float2*)&h[(size_t)r0 * DD + cc] = make_float2(dp[0], dp[1]);
                if (r1 < M) *(float2*)&h[(size_t)r1 * DD + cc] = make_float2(dp[2], dp[3]);
            } else {
                float b0v = __ldg(bf + boff + cc);
                float b1v = __ldg(bf + boff + cc + 1);
                if (r0 < M) *(float2*)&dstb[(size_t)r0 * DD + cc] = make_float2(dp[0] + b0v, dp[1] + b1v);
                if (r1 < M) *(float2*)&dstb[(size_t)r1 * DD + cc] = make_float2(dp[2] + b0v, dp[3] + b1v);
            }
        }
    }
}

// ---------------- aggregation + skip + combine: one warp per dst node -------
__global__ __launch_bounds__(256) void agg_combine_kernel(const int* __restrict__ base,
                                                          const int* __restrict__ srcs,
                                                          const float* __restrict__ h,
                                                          const float* __restrict__ gamma,
                                                          const float* __restrict__ beta,
                                                          const float* __restrict__ Y384,
                                                          const float* __restrict__ deginv,
                                                          float* __restrict__ xout,
                                                          int do_relu) {
    int node = (int)((blockIdx.x * blockDim.x + threadIdx.x) >> 5);
    int lane = threadIdx.x & 31;
    if (node >= NN) return;

    const float* yr = Y384 + (size_t)node * 384;
    float4 bs = __ldg((const float4*)(yr)       + lane);
    float4 gs = __ldg((const float4*)(yr + 128) + lane);
    float4 xs = __ldg((const float4*)(yr + 256) + lane);

    const float4 g = __ldg((const float4*)(gamma + (size_t)node * DD) + lane);
    const float4 b = __ldg((const float4*)(beta  + (size_t)node * DD) + lane);

    int e0 = __ldg(base + node);
    int e1 = __ldg(base + node + 1);

    float4 acc = make_float4(0.f, 0.f, 0.f, 0.f);
    int e = e0;

    int p0 = __ldg(srcs + e);
    int p1 = __ldg(srcs + e + 1);
    int p2 = __ldg(srcs + e + 2);
    int p3 = __ldg(srcs + e + 3);

    for (; e + 4 <= e1; e += 4) {
        int s0 = p0, s1 = p1, s2 = p2, s3 = p3;
        p0 = __ldg(srcs + e + 4);
        p1 = __ldg(srcs + e + 5);
        p2 = __ldg(srcs + e + 6);
        p3 = __ldg(srcs + e + 7);

        float4 h0 = __ldg((const float4*)(h + (size_t)s0 * DD) + lane);
        float4 h1 = __ldg((const float4*)(h + (size_t)s1 * DD) + lane);
        float4 h2 = __ldg((const float4*)(h + (size_t)s2 * DD) + lane);
        float4 h3 = __ldg((const float4*)(h + (size_t)s3 * DD) + lane);
        acc.x += fmaxf(fmaf(g.x, h0.x, b.x), 0.0f) + fmaxf(fmaf(g.x, h1.x, b.x), 0.0f)
               + fmaxf(fmaf(g.x, h2.x, b.x), 0.0f) + fmaxf(fmaf(g.x, h3.x, b.x), 0.0f);
        acc.y += fmaxf(fmaf(g.y, h0.y, b.y), 0.0f) + fmaxf(fmaf(g.y, h1.y, b.y), 0.0f)
               + fmaxf(fmaf(g.y, h2.y, b.y), 0.0f) + fmaxf(fmaf(g.y, h3.y, b.y), 0.0f);
        acc.z += fmaxf(fmaf(g.z, h0.z, b.z), 0.0f) + fmaxf(fmaf(g.z, h1.z, b.z), 0.0f)
               + fmaxf(fmaf(g.z, h2.z, b.z), 0.0f) + fmaxf(fmaf(g.z, h3.z, b.z), 0.0f);
        acc.w += fmaxf(fmaf(g.w, h0.w, b.w), 0.0f) + fmaxf(fmaf(g.w, h1.w, b.w), 0.0f)
               + fmaxf(fmaf(g.w, h2.w, b.w), 0.0f) + fmaxf(fmaf(g.w, h3.w, b.w), 0.0f);
    }

    int r = e1 - e;
    if (r > 0) {
        float4 h0 = __ldg((const float4*)(h + (size_t)p0 * DD) + lane);
        acc.x += fmaxf(fmaf(g.x, h0.x, b.x), 0.0f);
        acc.y += fmaxf(fmaf(g.y, h0.y, b.y), 0.0f);
        acc.z += fmaxf(fmaf(g.z, h0.z, b.z), 0.0f);
        acc.w += fmaxf(fmaf(g.w, h0.w, b.w), 0.0f);
    }
    if (r > 1) {
        float4 h1 = __ldg((const float4*)(h + (size_t)p1 * DD) + lane);
        acc.x += fmaxf(fmaf(g.x, h1.x, b.x), 0.0f);
        acc.y += fmaxf(fmaf(g.y, h1.y, b.y), 0.0f);
        acc.z += fmaxf(fmaf(g.z, h1.z, b.z), 0.0f);
        acc.w += fmaxf(fmaf(g.w, h1.w, b.w), 0.0f);
    }
    if (r > 2) {
        float4 h2 = __ldg((const float4*)(h + (size_t)p2 * DD) + lane);
        acc.x += fmaxf(fmaf(g.x, h2.x, b.x), 0.0f);
        acc.y += fmaxf(fmaf(g.y, h2.y, b.y), 0.0f);
        acc.z += fmaxf(fmaf(g.z, h2.z, b.z), 0.0f);
        acc.w += fmaxf(fmaf(g.w, h2.w, b.w), 0.0f);
    }

    float di = __ldg(deginv + node);
    float4 o;
    o.x = fmaxf(fmaf(gs.x, xs.x, bs.x), 0.0f);
    o.y = fmaxf(fmaf(gs.y, xs.y, bs.y), 0.0f);
    o.z = fmaxf(fmaf(gs.z, xs.z, bs.z), 0.0f);
    o.w = fmaxf(fmaf(gs.w, xs.w, bs.w), 0.0f);

    float4 res;
    res.x = o.x + acc.x * di;
    res.y = o.y + acc.y * di;
    res.z = o.z + acc.z * di;
    res.w = o.w + acc.w * di;
    if (do_relu) {
        res.x = fmaxf(res.x, 0.f); res.y = fmaxf(res.y, 0.f);
        res.z = fmaxf(res.z, 0.f); res.w = fmaxf(res.w, 0.f);
    }
    *((float4*)(xout + (size_t)node * DD) + lane) = res;
}

// ---------------- launch ----------------------------------------------------
extern "C" void kernel_launch(void* const* d_in, const int* in_sizes, int n_in,
                              void* d_out, int out_size) {
    const float* x       = (const float*)d_in[0];
    const void*  eidx    = d_in[1];
    const float* W_lin   = (const float*)d_in[2];
    const float* W_film  = (const float*)d_in[3];
    const float* b_film  = (const float*)d_in[4];
    const float* W_skip  = (const float*)d_in[5];
    const float* W_fskip = (const float*)d_in[6];
    float*       outp    = (float*)d_out;

    float *xhi, *xlo, *Wthi, *Wtlo, *Y, *ga, *be, *h, *xb0, *xb1, *deginv;
    int *counts, *base, *cursor, *srcs, *is64;
    cudaGetSymbolAddress((void**)&xhi,    g_xhi);
    cudaGetSymbolAddress((void**)&xlo,    g_xlo);
    cudaGetSymbolAddress((void**)&Wthi,   g_Wthi);
    cudaGetSymbolAddress((void**)&Wtlo,   g_Wtlo);
    cudaGetSymbolAddress((void**)&Y,      g_Y);
    cudaGetSymbolAddress((void**)&ga,     g_gamma);
    cudaGetSymbolAddress((void**)&be,     g_beta);
    cudaGetSymbolAddress((void**)&h,      g_h);
    cudaGetSymbolAddress((void**)&xb0,    g_xb0);
    cudaGetSymbolAddress((void**)&xb1,    g_xb1);
    cudaGetSymbolAddress((void**)&deginv, g_deginv);
    cudaGetSymbolAddress((void**)&counts, g_counts);
    cudaGetSymbolAddress((void**)&base,   g_base);
    cudaGetSymbolAddress((void**)&cursor, g_cursor);
    cudaGetSymbolAddress((void**)&srcs,   g_srcs);
    cudaGetSymbolAddress((void**)&is64,   g_is64);

    // dtype probe + pack weights (transposed, tf32 hi/lo)
    detect_kernel<<<1, 1>>>(eidx, is64);
    {
        int tot = NLAYERS * NCAT * DD;
        pack_weights_kernel<<<(tot + 255) / 256, 256>>>(W_lin, W_film, W_skip, W_fskip,
                                                        Wthi, Wtlo);
    }

    // CSR build (by dst)
    zero_int_kernel<<<(NN + 255) / 256, 256>>>(counts, NN);
    count_kernel<<<(EE + 255) / 256, 256>>>(eidx, is64, counts);
    scan_kernel<<<1, 1024>>>(counts, base, cursor, deginv);
    scatter_kernel<<<(EE + 255) / 256, 256>>>(eidx, is64, cursor, srcs);

    const int elemBlocks = (NN * DD + 255) / 256;
    const int nodeWarpBlocks = (NN * 32 + 255) / 256;
    dim3 gemmGrid(6, MT);

    const float* xin = x;
    for (int l = 0; l < NLAYERS; l++) {
        split_kernel<<<elemBlocks, 256>>>(xin, xhi, xlo);
        gemm_tf32_kernel<<<gemmGrid, 256>>>(xhi, xlo,
                                            Wthi + (size_t)l * NCAT * DD,
                                            Wtlo + (size_t)l * NCAT * DD,
                                            b_film + (size_t)l * 256,
                                            Y, be, ga, h, NN);

        float* xout;
        if (l == NLAYERS - 1)      xout = outp;
        else if ((l & 1) == 0)     xout = xb0;
        else                       xout = xb1;

        agg_combine_kernel<<<nodeWarpBlocks, 256>>>(base, srcs, h, ga, be, Y, deginv,
                                                    xout, (l < NLAYERS - 1) ? 1 : 0);
        xin = xout;
    }
}